// round 16
// baseline (speedup 1.0000x reference)
#include <cuda_runtime.h>
#include <cstdint>

// Problem constants
#define TSEQ   2048
#define NB     2
#define BT     4096      // NB*TSEQ
#define DM     1024
#define D3     3072
#define NH     16
#define HD     64        // head dim

// Scratch (device globals: no allocation allowed in kernel_launch)
__device__ float g_kqv[(size_t)BT * D3];   // [B*T, 3d]  cols: [0,1024)=K, [1024,2048)=Q, [2048,3072)=V (tf32)
__device__ float g_att[(size_t)BT * DM];   // attention output [B*T, d] (tf32)
__device__ float g_xa [(size_t)BT * DM];   // x, tf32-rounded
__device__ float g_wk [(size_t)DM * D3];   // W_kqv, tf32-rounded ([K=1024, N=3072])
__device__ float g_wo [(size_t)DM * DM];   // W_o,   tf32-rounded
__device__ float g_vt [(size_t)NB * NH * HD * TSEQ];  // V transposed: [b][h][c][t]

// ============================================================================
// helpers
// ============================================================================
__device__ __forceinline__ uint32_t smem_u32(const void* p) {
    uint32_t a;
    asm("{ .reg .u64 t; cvta.to.shared.u64 t, %1; cvt.u32.u64 %0, t; }" : "=r"(a) : "l"(p));
    return a;
}
__device__ __forceinline__ float tf32_rna(float x) {
    uint32_t u;
    asm("cvt.rna.tf32.f32 %0, %1;" : "=r"(u) : "f"(x));
    return __uint_as_float(u);
}

// m16n8k8 tf32 mma: D = A(16x8, row) * B(8x8, col) + D
#define MMA_TF32(c, a0, a1, a2, a3, b0, b1)                                   \
    asm volatile("mma.sync.aligned.m16n8k8.row.col.f32.tf32.tf32.f32 "        \
        "{%0,%1,%2,%3}, {%4,%5,%6,%7}, {%8,%9}, {%0,%1,%2,%3};"               \
        : "+f"((c)[0]), "+f"((c)[1]), "+f"((c)[2]), "+f"((c)[3])              \
        : "r"(a0), "r"(a1), "r"(a2), "r"(a3), "r"(b0), "r"(b1))

// ldmatrix x4: 4 8x8-b16 matrices (= 8x4 tf32 each)
#define LDSM_X4(r0, r1, r2, r3, addr)                                         \
    asm volatile("ldmatrix.sync.aligned.m8n8.x4.shared.b16 {%0,%1,%2,%3}, [%4];" \
        : "=r"(r0), "=r"(r1), "=r"(r2), "=r"(r3) : "r"(addr))

#define CP_ASYNC16(dst, src) \
    asm volatile("cp.async.cg.shared.global [%0], [%1], 16;" :: "r"(dst), "l"(src))
#define CP_COMMIT()  asm volatile("cp.async.commit_group;" ::: "memory")
#define CP_WAIT0()   asm volatile("cp.async.wait_group 0;" ::: "memory")
#define CP_WAIT1()   asm volatile("cp.async.wait_group 1;" ::: "memory")
#define CP_WAIT2()   asm volatile("cp.async.wait_group 2;" ::: "memory")

// ============================================================================
// Prep: merged tf32-rounding pass over x, W_kqv, W_o (R11 form)
// ============================================================================
#define N_X  (BT * DM / 4)                      // 1048576 float4
#define N_WK (DM * D3 / 4)                      // 786432
#define N_WO (DM * DM / 4)                      // 262144
#define N_PREP (N_X + N_WK + N_WO)              // 2097152

__global__ void round_all_kernel(const float* __restrict__ x,
                                 const float* __restrict__ Wk,
                                 const float* __restrict__ Wo) {
    const int i = blockIdx.x * blockDim.x + threadIdx.x;
    const float4* src;
    float4* dst;
    int j = i;
    if (i < N_X) {
        src = reinterpret_cast<const float4*>(x);
        dst = reinterpret_cast<float4*>(g_xa);
    } else if (i < N_X + N_WK) {
        j = i - N_X;
        src = reinterpret_cast<const float4*>(Wk);
        dst = reinterpret_cast<float4*>(g_wk);
    } else {
        j = i - N_X - N_WK;
        src = reinterpret_cast<const float4*>(Wo);
        dst = reinterpret_cast<float4*>(g_wo);
    }
    float4 v = src[j];
    v.x = tf32_rna(v.x); v.y = tf32_rna(v.y);
    v.z = tf32_rna(v.z); v.w = tf32_rna(v.w);
    dst[j] = v;
}

// ============================================================================
// V transpose: g_vt[b][h][c][t] = g_kqv[b*T+t][2*DM + h*64 + c]
// 32x32 tiles, block (32,8). grid (T/32, HD/32, NB*NH).
// ============================================================================
__global__ void transpose_v_kernel() {
    __shared__ float t[32][33];
    const int t0 = blockIdx.x * 32;
    const int c0 = blockIdx.y * 32;
    const int bh = blockIdx.z;            // b*NH + h
    const int b  = bh >> 4, h = bh & 15;
    const int tx = threadIdx.x, ty = threadIdx.y;
    #pragma unroll
    for (int i = 0; i < 32; i += 8)
        t[ty + i][tx] = g_kqv[(size_t)(b * TSEQ + t0 + ty + i) * D3
                              + 2 * DM + h * HD + c0 + tx];
    __syncthreads();
    #pragma unroll
    for (int i = 0; i < 32; i += 8)
        g_vt[((size_t)bh * HD + c0 + ty + i) * TSEQ + t0 + tx] = t[tx][ty + i];
}

// ============================================================================
// GEMM (mma.sync tf32):  C[M,N] = A[M,K] @ W[K,N] + bias[N]
// R7/R11 pipeline (measured fastest — frozen): issue-before-wait, CP_WAIT1,
// 2 barriers, A-frags via ldmatrix.x4, B scalar.
// 256 thr = 8 warps, warp tile 64x32. smem: As[2][128][36]+Bs[2][32][136]
// ============================================================================
#define G_SMEM_BYTES ((2 * 128 * 36 + 2 * 32 * 136) * 4)   // 71680

__global__ __launch_bounds__(256, 2) void gemm_mma_kernel(
    const float* __restrict__ A, const float* __restrict__ W,
    const float* __restrict__ bias, float* __restrict__ C,
    int M, int N, int K, int round_out)
{
    extern __shared__ float sm[];
    float* As = sm;                  // [2][128][36]
    float* Bs = sm + 2 * 128 * 36;   // [2][32][136]

    const int tid  = threadIdx.x;
    const int wid  = tid >> 5;
    const int lane = tid & 31;
    const int g    = lane >> 2;      // groupID 0..7
    const int tig  = lane & 3;       // thread-in-group 0..3
    const int m0 = blockIdx.y * 128;
    const int n0 = blockIdx.x * 128;
    const int wm = (wid >> 2) * 64;  // warp m offset (0/64)
    const int wn = (wid & 3) * 32;   // warp n offset

    const uint32_t as_base = smem_u32(As);
    const uint32_t a_lane_off =
        ((uint32_t)(wm + (lane & 15)) * 36 + ((lane >> 2) & 4)) * 4;

    float acc[4][4][4];
    #pragma unroll
    for (int mt = 0; mt < 4; mt++)
        #pragma unroll
        for (int nt = 0; nt < 4; nt++)
            #pragma unroll
            for (int e = 0; e < 4; e++) acc[mt][nt][e] = 0.0f;

    const int nchunk = K / 32;

    auto issue = [&](int ch, int s) {
        #pragma unroll
        for (int i = 0; i < 4; i++) {
            const int idx = tid + i * 256;            // 0..1023
            const int r = idx >> 3, c4 = (idx & 7) * 4;
            CP_ASYNC16(smem_u32(&As[s * 4608 + r * 36 + c4]),
                       &A[(size_t)(m0 + r) * K + ch * 32 + c4]);
        }
        #pragma unroll
        for (int i = 0; i < 4; i++) {
            const int idx = tid + i * 256;
            const int r = idx >> 5, c4 = (idx & 31) * 4;
            CP_ASYNC16(smem_u32(&Bs[s * 4352 + r * 136 + c4]),
                       &W[(size_t)(ch * 32 + r) * N + n0 + c4]);
        }
        CP_COMMIT();
    };

    issue(0, 0);
    for (int ch = 0; ch < nchunk; ch++) {
        const int s = ch & 1;
        if (ch + 1 < nchunk) { issue(ch + 1, s ^ 1); CP_WAIT1(); }
        else                 { CP_WAIT0(); }
        __syncthreads();

        const float* bs = Bs + s * 4352;
        const uint32_t a_addr = as_base + (uint32_t)s * 4608 * 4 + a_lane_off;
        #pragma unroll
        for (int ks = 0; ks < 4; ks++) {
            const int k = ks * 8;
            uint32_t a[4][4];
            #pragma unroll
            for (int mt = 0; mt < 4; mt++)
                LDSM_X4(a[mt][0], a[mt][1], a[mt][2], a[mt][3],
                        a_addr + (uint32_t)(mt * 576 + k) * 4);
            #pragma unroll
            for (int nt = 0; nt < 4; nt++) {
                const float* bp = bs + (k + tig) * 136 + wn + nt * 8 + g;
                const uint32_t b0 = __float_as_uint(bp[0]);
                const uint32_t b1 = __float_as_uint(bp[4 * 136]);
                #pragma unroll
                for (int mt = 0; mt < 4; mt++)
                    MMA_TF32(acc[mt][nt], a[mt][0], a[mt][1], a[mt][2], a[mt][3], b0, b1);
            }
        }
        __syncthreads();
    }

    #pragma unroll
    for (int mt = 0; mt < 4; mt++) {
        const int r_lo = m0 + wm + mt * 16 + g;
        const int r_hi = r_lo + 8;
        #pragma unroll
        for (int nt = 0; nt < 4; nt++) {
            const int c = n0 + wn + nt * 8 + 2 * tig;
            const float b0 = bias[c], b1 = bias[c + 1];
            float v0 = acc[mt][nt][0] + b0;
            float v1 = acc[mt][nt][1] + b1;
            float v2 = acc[mt][nt][2] + b0;
            float v3 = acc[mt][nt][3] + b1;
            if (round_out) {
                v0 = tf32_rna(v0); v1 = tf32_rna(v1);
                v2 = tf32_rna(v2); v3 = tf32_rna(v3);
            }
            *reinterpret_cast<float2*>(&C[(size_t)r_lo * N + c]) = make_float2(v0, v1);
            *reinterpret_cast<float2*>(&C[(size_t)r_hi * N + c]) = make_float2(v2, v3);
        }
    }
}

// ============================================================================
// Flash attention: R11 config + TRANSPOSED V (Vs is [c][t] stride 68 — the
// validated K-operand ldmatrix layout). PV loop now fully LDSM-fed:
// 128 scalar LDS/tile/thread -> 32 LDSM_X4.
// smem: Qs/Ps[64][68] + Ks[2][64][68] + Vs[64][68] = 69632 B -> 3 CTAs/SM
// ============================================================================
#define ASC 0.18033688011112042f     // 0.125 * log2(e)
#define PS  68
#define A_SMEM_BYTES ((4352 + 2 * 4352 + 4352) * 4)   // 69632

__global__ __launch_bounds__(128, 3) void attn_mma_kernel()
{
    extern __shared__ float sm[];
    float* Qs = sm;               // [64][68] — becomes Ps after Q-frag hoist
    float* Ks = sm + 4352;        // [2][64][68]  stage stride 4352
    float* Vs = sm + 13056;       // [64][68]  Vt tile: rows=c, cols=t (single buffer)
    float* Ps = Qs;

    const int tid  = threadIdx.x;
    const int wid  = tid >> 5;
    const int lane = tid & 31;
    const int g    = lane >> 2;
    const int tig  = lane & 3;
    const int qb = gridDim.x - 1 - blockIdx.x;   // heavy CTAs first
    const int h  = blockIdx.y;
    const int b  = blockIdx.z;
    const int q0 = qb * 64;
    const int wr = wid * 16;                 // warp's q-row base within tile
    const int r_lo_g = q0 + wr + g;          // global q row (lo)
    const int r_hi_g = r_lo_g + 8;

    const uint32_t a_lane_off =
        ((uint32_t)(wr + (lane & 15)) * 68 + ((lane >> 2) & 4)) * 4;
    const uint32_t k_lane_off =
        ((uint32_t)(((lane & 7) + ((lane & 16) ? 8 : 0)) * 68)
         + ((lane & 8) ? 4 : 0)) * 4;

    auto issue_k = [&](int tile, int st) {
        const int s0 = tile * 64;
        #pragma unroll
        for (int i = 0; i < 8; i++) {
            const int idx = tid + i * 128;
            const int r = idx >> 4, c4 = (idx & 15) * 4;
            CP_ASYNC16(smem_u32(&Ks[st * 4352 + r * 68 + c4]),
                       &g_kqv[(size_t)(b * TSEQ + s0 + r) * D3 + h * HD + c4]);
        }
        CP_COMMIT();
    };
    // V tile from g_vt: row r = channel c, cols = tokens (contiguous)
    auto issue_v = [&](int tile) {
        const int s0 = tile * 64;
        const size_t vbase = (size_t)(b * NH + h) * HD * TSEQ;
        #pragma unroll
        for (int i = 0; i < 8; i++) {
            const int idx = tid + i * 128;
            const int r = idx >> 4, c4 = (idx & 15) * 4;
            CP_ASYNC16(smem_u32(&Vs[r * 68 + c4]),
                       &g_vt[vbase + (size_t)r * TSEQ + s0 + c4]);
        }
        CP_COMMIT();
    };

    // prologue: K(0) then V(0) in flight
    issue_k(0, 0);
    issue_v(0);

    // Load Q tile (plain LDG->STS; rounded tf32 already)
    #pragma unroll
    for (int i = 0; i < 8; i++) {
        const int idx = tid + i * 128;
        const int r = idx >> 4, c4 = (idx & 15) * 4;
        *reinterpret_cast<float4*>(&Qs[r * 68 + c4]) =
            *reinterpret_cast<const float4*>(
                &g_kqv[(size_t)(b * TSEQ + q0 + r) * D3 + DM + h * HD + c4]);
    }
    __syncthreads();   // Qs visible -> hoist Q fragments, then Qs region is Ps

    uint32_t qf[8][4];
    {
        const uint32_t q_addr = smem_u32(Qs) + a_lane_off;
        #pragma unroll
        for (int ksn = 0; ksn < 8; ksn++)
            LDSM_X4(qf[ksn][0], qf[ksn][1], qf[ksn][2], qf[ksn][3],
                    q_addr + (uint32_t)ksn * 32);
    }

    float o[8][4];
    #pragma unroll
    for (int nt = 0; nt < 8; nt++)
        #pragma unroll
        for (int e = 0; e < 4; e++) o[nt][e] = 0.0f;
    float m_lo = -1e30f, m_hi = -1e30f, l_lo = 0.0f, l_hi = 0.0f;

    const uint32_t p_addr = smem_u32(Ps) + a_lane_off;
    const uint32_t v_addr = smem_u32(Vs) + k_lane_off;

    for (int tile = 0; tile <= qb; tile++) {
        const int s0 = tile * 64;
        const int st = tile & 1;
        const bool more = (tile + 1 <= qb);
        if (more) { issue_k(tile + 1, st ^ 1); CP_WAIT2(); }  // allow {V(t), K(t+1)}
        else      { CP_WAIT1(); }                              // allow {V(t)}
        __syncthreads();     // K(st) visible

        const uint32_t k_addr = smem_u32(Ks) + (uint32_t)st * 4352 * 4 + k_lane_off;

        // ---- S = Q @ K^T ----
        float sacc[8][4];
        #pragma unroll
        for (int nt = 0; nt < 8; nt++)
            #pragma unroll
            for (int e = 0; e < 4; e++) sacc[nt][e] = 0.0f;

        #pragma unroll
        for (int ksn = 0; ksn < 8; ksn++) {
            const int k = ksn * 8;
            #pragma unroll
            for (int nt = 0; nt < 8; nt += 2) {
                uint32_t b0a, b1a, b0b, b1b;
                LDSM_X4(b0a, b1a, b0b, b1b,
                        k_addr + (uint32_t)(nt * 8 * 68 + k) * 4);
                MMA_TF32(sacc[nt],     qf[ksn][0], qf[ksn][1], qf[ksn][2], qf[ksn][3], b0a, b1a);
                MMA_TF32(sacc[nt + 1], qf[ksn][0], qf[ksn][1], qf[ksn][2], qf[ksn][3], b0b, b1b);
            }
        }

        // ---- scale (log2 domain) + causal mask (diagonal tile only) ----
        const bool masked = (tile == qb);
        #pragma unroll
        for (int nt = 0; nt < 8; nt++) {
            float v0 = sacc[nt][0] * ASC, v1 = sacc[nt][1] * ASC;
            float v2 = sacc[nt][2] * ASC, v3 = sacc[nt][3] * ASC;
            if (masked) {
                const int c0 = s0 + nt * 8 + 2 * tig, c1 = c0 + 1;
                if (c0 > r_lo_g) v0 = -1e30f;
                if (c1 > r_lo_g) v1 = -1e30f;
                if (c0 > r_hi_g) v2 = -1e30f;
                if (c1 > r_hi_g) v3 = -1e30f;
            }
            sacc[nt][0] = v0; sacc[nt][1] = v1; sacc[nt][2] = v2; sacc[nt][3] = v3;
        }

        // ---- online softmax ----
        float xl = -1e30f, xh = -1e30f;
        #pragma unroll
        for (int nt = 0; nt < 8; nt++) {
            xl = fmaxf(xl, fmaxf(sacc[nt][0], sacc[nt][1]));
            xh = fmaxf(xh, fmaxf(sacc[nt][2], sacc[nt][3]));
        }
        xl = fmaxf(xl, __shfl_xor_sync(0xFFFFFFFFu, xl, 1));
        xl = fmaxf(xl, __shfl_xor_sync(0xFFFFFFFFu, xl, 2));
        xh = fmaxf(xh, __shfl_xor_sync(0xFFFFFFFFu, xh, 1));
        xh = fmaxf(xh, __shfl_xor_sync(0xFFFFFFFFu, xh, 2));
        const float mn_lo = fmaxf(m_lo, xl);
        const float mn_hi = fmaxf(m_hi, xh);
        const float al = exp2f(m_lo - mn_lo);
        const float ah = exp2f(m_hi - mn_hi);
        m_lo = mn_lo; m_hi = mn_hi;

        float sl = 0.0f, sh = 0.0f;
        #pragma unroll
        for (int nt = 0; nt < 8; nt++) {
            const float p0 = exp2f(sacc[nt][0] - mn_lo);
            const float p1 = exp2f(sacc[nt][1] - mn_lo);
            const float p2 = exp2f(sacc[nt][2] - mn_hi);
            const float p3 = exp2f(sacc[nt][3] - mn_hi);
            sl += p0 + p1; sh += p2 + p3;
            const int c = nt * 8 + 2 * tig;
            *reinterpret_cast<float2*>(&Ps[(wr + g) * PS + c]) =
                make_float2(tf32_rna(p0), tf32_rna(p1));
            *reinterpret_cast<float2*>(&Ps[(wr + g + 8) * PS + c]) =
                make_float2(tf32_rna(p2), tf32_rna(p3));
        }
        sl += __shfl_xor_sync(0xFFFFFFFFu, sl, 1);
        sl += __shfl_xor_sync(0xFFFFFFFFu, sl, 2);
        sh += __shfl_xor_sync(0xFFFFFFFFu, sh, 1);
        sh += __shfl_xor_sync(0xFFFFFFFFu, sh, 2);
        l_lo = l_lo * al + sl;
        l_hi = l_hi * ah + sh;
        #pragma unroll
        for (int nt = 0; nt < 8; nt++) {
            o[nt][0] *= al; o[nt][1] *= al;
            o[nt][2] *= ah; o[nt][3] *= ah;
        }
        __syncwarp();

        // ---- wait V(t), then O += P @ V (fully ldmatrix-fed) ----
        if (more) CP_WAIT1(); else CP_WAIT0();   // allow K(t+1) only
        __syncthreads();     // V visible to all threads

        #pragma unroll
        for (int ksn = 0; ksn < 8; ksn++) {
            const int k = ksn * 8;
            uint32_t pa0, pa1, pa2, pa3;
            LDSM_X4(pa0, pa1, pa2, pa3, p_addr + (uint32_t)ksn * 32);
            #pragma unroll
            for (int nt = 0; nt < 8; nt += 2) {
                uint32_t b0a, b1a, b0b, b1b;
                LDSM_X4(b0a, b1a, b0b, b1b,
                        v_addr + (uint32_t)(nt * 8 * 68 + k) * 4);
                MMA_TF32(o[nt],     pa0, pa1, pa2, pa3, b0a, b1a);
                MMA_TF32(o[nt + 1], pa0, pa1, pa2, pa3, b0b, b1b);
            }
        }
        __syncthreads();     // all warps done reading Vs before refill
        if (more) issue_v(tile + 1);
    }

    // epilogue: normalize, round to tf32 (GEMM2 consumes as A), store
    const float il = 1.0f / l_lo;
    const float ih = 1.0f / l_hi;
    #pragma unroll
    for (int nt = 0; nt < 8; nt++) {
        const int c = h * HD + nt * 8 + 2 * tig;
        *reinterpret_cast<float2*>(&g_att[(size_t)(b * TSEQ + r_lo_g) * DM + c]) =
            make_float2(tf32_rna(o[nt][0] * il), tf32_rna(o[nt][1] * il));
        *reinterpret_cast<float2*>(&g_att[(size_t)(b * TSEQ + r_hi_g) * DM + c]) =
            make_float2(tf32_rna(o[nt][2] * ih), tf32_rna(o[nt][3] * ih));
    }
}

// ----------------------------------------------------------------------------
extern "C" void kernel_launch(void* const* d_in, const int* in_sizes, int n_in,
                              void* d_out, int out_size)
{
    (void)in_sizes; (void)n_in; (void)out_size;
    const float* x     = (const float*)d_in[0];
    const float* W_kqv = (const float*)d_in[1];
    const float* b_kqv = (const float*)d_in[2];
    const float* W_o   = (const float*)d_in[3];
    const float* b_o   = (const float*)d_in[4];
    float* out = (float*)d_out;

    float *kqv_p, *att_p, *xa_p, *wk_p, *wo_p;
    cudaGetSymbolAddress((void**)&kqv_p, g_kqv);
    cudaGetSymbolAddress((void**)&att_p, g_att);
    cudaGetSymbolAddress((void**)&xa_p,  g_xa);
    cudaGetSymbolAddress((void**)&wk_p,  g_wk);
    cudaGetSymbolAddress((void**)&wo_p,  g_wo);

    cudaFuncSetAttribute(gemm_mma_kernel,
                         cudaFuncAttributeMaxDynamicSharedMemorySize, G_SMEM_BYTES);
    cudaFuncSetAttribute(attn_mma_kernel,
                         cudaFuncAttributeMaxDynamicSharedMemorySize, A_SMEM_BYTES);

    // prep: merged tf32 rounding pass (x, W_kqv, W_o)
    round_all_kernel<<<N_PREP / 256, 256>>>(x, W_kqv, W_o);

    // 1) KQV projection (outputs rounded to tf32 for attention)
    gemm_mma_kernel<<<dim3(D3 / 128, BT / 128), 256, G_SMEM_BYTES>>>(
        xa_p, wk_p, b_kqv, kqv_p, BT, D3, DM, 1);
    // 1b) transpose V into [b][h][c][t] for ldmatrix-fed PV
    transpose_v_kernel<<<dim3(TSEQ / 32, HD / 32, NB * NH), dim3(32, 8)>>>();
    // 2) Causal flash attention (occ 3, K double-buffer, LDSM V)
    attn_mma_kernel<<<dim3(TSEQ / 64, NH, NB), 128, A_SMEM_BYTES>>>();
    // 3) Output projection
    gemm_mma_kernel<<<dim3(DM / 128, BT / 128), 256, G_SMEM_BYTES>>>(
        att_p, wo_p, b_o, out, BT, DM, DM, 0);
}

// round 17
// speedup vs baseline: 1.0130x; 1.0130x over previous
#include <cuda_runtime.h>
#include <cstdint>

// Problem constants
#define TSEQ   2048
#define NB     2
#define BT     4096      // NB*TSEQ
#define DM     1024
#define D3     3072
#define NH     16
#define HD     64        // head dim

// Scratch (device globals: no allocation allowed in kernel_launch)
__device__ float g_kqv[(size_t)BT * D3];   // [B*T, 3d]  cols: [0,1024)=K, [1024,2048)=Q, [2048,3072)=V (tf32)
__device__ float g_att[(size_t)BT * DM];   // attention output [B*T, d] (tf32)
__device__ float g_xa [(size_t)BT * DM];   // x, tf32-rounded
__device__ float g_wk [(size_t)DM * D3];   // W_kqv, tf32-rounded ([K=1024, N=3072])
__device__ float g_wo [(size_t)DM * DM];   // W_o,   tf32-rounded

// ============================================================================
// helpers
// ============================================================================
__device__ __forceinline__ uint32_t smem_u32(const void* p) {
    uint32_t a;
    asm("{ .reg .u64 t; cvta.to.shared.u64 t, %1; cvt.u32.u64 %0, t; }" : "=r"(a) : "l"(p));
    return a;
}
__device__ __forceinline__ float tf32_rna(float x) {
    uint32_t u;
    asm("cvt.rna.tf32.f32 %0, %1;" : "=r"(u) : "f"(x));
    return __uint_as_float(u);
}

// m16n8k8 tf32 mma: D = A(16x8, row) * B(8x8, col) + D
#define MMA_TF32(c, a0, a1, a2, a3, b0, b1)                                   \
    asm volatile("mma.sync.aligned.m16n8k8.row.col.f32.tf32.tf32.f32 "        \
        "{%0,%1,%2,%3}, {%4,%5,%6,%7}, {%8,%9}, {%0,%1,%2,%3};"               \
        : "+f"((c)[0]), "+f"((c)[1]), "+f"((c)[2]), "+f"((c)[3])              \
        : "r"(a0), "r"(a1), "r"(a2), "r"(a3), "r"(b0), "r"(b1))

// ldmatrix x4: 4 8x8-b16 matrices (= 8x4 tf32 each)
#define LDSM_X4(r0, r1, r2, r3, addr)                                         \
    asm volatile("ldmatrix.sync.aligned.m8n8.x4.shared.b16 {%0,%1,%2,%3}, [%4];" \
        : "=r"(r0), "=r"(r1), "=r"(r2), "=r"(r3) : "r"(addr))

#define CP_ASYNC16(dst, src) \
    asm volatile("cp.async.cg.shared.global [%0], [%1], 16;" :: "r"(dst), "l"(src))
#define CP_COMMIT()  asm volatile("cp.async.commit_group;" ::: "memory")
#define CP_WAIT0()   asm volatile("cp.async.wait_group 0;" ::: "memory")
#define CP_WAIT1()   asm volatile("cp.async.wait_group 1;" ::: "memory")
#define CP_WAIT2()   asm volatile("cp.async.wait_group 2;" ::: "memory")

// ============================================================================
// Prep: single merged tf32-rounding pass over x, W_kqv, W_o
// ============================================================================
#define N_X  (BT * DM / 4)                      // 1048576 float4
#define N_WK (DM * D3 / 4)                      // 786432
#define N_WO (DM * DM / 4)                      // 262144
#define N_PREP (N_X + N_WK + N_WO)              // 2097152

__global__ void round_all_kernel(const float* __restrict__ x,
                                 const float* __restrict__ Wk,
                                 const float* __restrict__ Wo) {
    const int i = blockIdx.x * blockDim.x + threadIdx.x;
    const float4* src;
    float4* dst;
    int j = i;
    if (i < N_X) {
        src = reinterpret_cast<const float4*>(x);
        dst = reinterpret_cast<float4*>(g_xa);
    } else if (i < N_X + N_WK) {
        j = i - N_X;
        src = reinterpret_cast<const float4*>(Wk);
        dst = reinterpret_cast<float4*>(g_wk);
    } else {
        j = i - N_X - N_WK;
        src = reinterpret_cast<const float4*>(Wo);
        dst = reinterpret_cast<float4*>(g_wo);
    }
    float4 v = src[j];
    v.x = tf32_rna(v.x); v.y = tf32_rna(v.y);
    v.z = tf32_rna(v.z); v.w = tf32_rna(v.w);
    dst[j] = v;
}

// ============================================================================
// GEMM (mma.sync tf32):  C[M,N] = A[M,K] @ W[K,N] + bias[N]
// R7/R11 pipeline (measured fastest — frozen): issue-before-wait, CP_WAIT1,
// 2 barriers, A-frags via ldmatrix.x4, B scalar.
// 256 thr = 8 warps, warp tile 64x32. smem: As[2][128][36]+Bs[2][32][136]
// ============================================================================
#define G_SMEM_BYTES ((2 * 128 * 36 + 2 * 32 * 136) * 4)   // 71680

__global__ __launch_bounds__(256, 2) void gemm_mma_kernel(
    const float* __restrict__ A, const float* __restrict__ W,
    const float* __restrict__ bias, float* __restrict__ C,
    int M, int N, int K, int round_out)
{
    extern __shared__ float sm[];
    float* As = sm;                  // [2][128][36]
    float* Bs = sm + 2 * 128 * 36;   // [2][32][136]

    const int tid  = threadIdx.x;
    const int wid  = tid >> 5;
    const int lane = tid & 31;
    const int g    = lane >> 2;      // groupID 0..7
    const int tig  = lane & 3;       // thread-in-group 0..3
    const int m0 = blockIdx.y * 128;
    const int n0 = blockIdx.x * 128;
    const int wm = (wid >> 2) * 64;  // warp m offset (0/64)
    const int wn = (wid & 3) * 32;   // warp n offset

    const uint32_t as_base = smem_u32(As);
    const uint32_t a_lane_off =
        ((uint32_t)(wm + (lane & 15)) * 36 + ((lane >> 2) & 4)) * 4;

    float acc[4][4][4];
    #pragma unroll
    for (int mt = 0; mt < 4; mt++)
        #pragma unroll
        for (int nt = 0; nt < 4; nt++)
            #pragma unroll
            for (int e = 0; e < 4; e++) acc[mt][nt][e] = 0.0f;

    const int nchunk = K / 32;

    auto issue = [&](int ch, int s) {
        #pragma unroll
        for (int i = 0; i < 4; i++) {
            const int idx = tid + i * 256;            // 0..1023
            const int r = idx >> 3, c4 = (idx & 7) * 4;
            CP_ASYNC16(smem_u32(&As[s * 4608 + r * 36 + c4]),
                       &A[(size_t)(m0 + r) * K + ch * 32 + c4]);
        }
        #pragma unroll
        for (int i = 0; i < 4; i++) {
            const int idx = tid + i * 256;
            const int r = idx >> 5, c4 = (idx & 31) * 4;
            CP_ASYNC16(smem_u32(&Bs[s * 4352 + r * 136 + c4]),
                       &W[(size_t)(ch * 32 + r) * N + n0 + c4]);
        }
        CP_COMMIT();
    };

    issue(0, 0);
    for (int ch = 0; ch < nchunk; ch++) {
        const int s = ch & 1;
        if (ch + 1 < nchunk) { issue(ch + 1, s ^ 1); CP_WAIT1(); }
        else                 { CP_WAIT0(); }
        __syncthreads();

        const float* bs = Bs + s * 4352;
        const uint32_t a_addr = as_base + (uint32_t)s * 4608 * 4 + a_lane_off;
        #pragma unroll
        for (int ks = 0; ks < 4; ks++) {
            const int k = ks * 8;
            uint32_t a[4][4];
            #pragma unroll
            for (int mt = 0; mt < 4; mt++)
                LDSM_X4(a[mt][0], a[mt][1], a[mt][2], a[mt][3],
                        a_addr + (uint32_t)(mt * 576 + k) * 4);
            #pragma unroll
            for (int nt = 0; nt < 4; nt++) {
                const float* bp = bs + (k + tig) * 136 + wn + nt * 8 + g;
                const uint32_t b0 = __float_as_uint(bp[0]);
                const uint32_t b1 = __float_as_uint(bp[4 * 136]);
                #pragma unroll
                for (int mt = 0; mt < 4; mt++)
                    MMA_TF32(acc[mt][nt], a[mt][0], a[mt][1], a[mt][2], a[mt][3], b0, b1);
            }
        }
        __syncthreads();
    }

    #pragma unroll
    for (int mt = 0; mt < 4; mt++) {
        const int r_lo = m0 + wm + mt * 16 + g;
        const int r_hi = r_lo + 8;
        #pragma unroll
        for (int nt = 0; nt < 4; nt++) {
            const int c = n0 + wn + nt * 8 + 2 * tig;
            const float b0 = bias[c], b1 = bias[c + 1];
            float v0 = acc[mt][nt][0] + b0;
            float v1 = acc[mt][nt][1] + b1;
            float v2 = acc[mt][nt][2] + b0;
            float v3 = acc[mt][nt][3] + b1;
            if (round_out) {
                v0 = tf32_rna(v0); v1 = tf32_rna(v1);
                v2 = tf32_rna(v2); v3 = tf32_rna(v3);
            }
            *reinterpret_cast<float2*>(&C[(size_t)r_lo * N + c]) = make_float2(v0, v1);
            *reinterpret_cast<float2*>(&C[(size_t)r_hi * N + c]) = make_float2(v2, v3);
        }
    }
}

// ============================================================================
// Flash attention (R11 config — measured best, frozen): mma.sync tf32 +
// ldmatrix, BR=64, 128 thr, occupancy 3. Q hoisted to regs; P aliases Qs.
// K double-buffered, V single-buffered with split wait.
// smem: Qs/Ps[64][68] + Ks[2][64][68] + Vs[64][72] = 70656 B -> 3 CTAs/SM
// ============================================================================
#define ASC 0.18033688011112042f     // 0.125 * log2(e)
#define PS  68
#define A_SMEM_BYTES ((4352 + 2 * 4352 + 4608) * 4)   // 70656

__global__ __launch_bounds__(128, 3) void attn_mma_kernel()
{
    extern __shared__ float sm[];
    float* Qs = sm;               // [64][68] — becomes Ps after Q-frag hoist
    float* Ks = sm + 4352;        // [2][64][68]  stage stride 4352
    float* Vs = sm + 13056;       // [64][72]  (single buffer)
    float* Ps = Qs;

    const int tid  = threadIdx.x;
    const int wid  = tid >> 5;
    const int lane = tid & 31;
    const int g    = lane >> 2;
    const int tig  = lane & 3;
    const int qb = gridDim.x - 1 - blockIdx.x;   // heavy CTAs first
    const int h  = blockIdx.y;
    const int b  = blockIdx.z;
    const int q0 = qb * 64;
    const int wr = wid * 16;                 // warp's q-row base within tile
    const int r_lo_g = q0 + wr + g;          // global q row (lo)
    const int r_hi_g = r_lo_g + 8;

    const uint32_t a_lane_off =
        ((uint32_t)(wr + (lane & 15)) * 68 + ((lane >> 2) & 4)) * 4;
    const uint32_t k_lane_off =
        ((uint32_t)(((lane & 7) + ((lane & 16) ? 8 : 0)) * 68)
         + ((lane & 8) ? 4 : 0)) * 4;

    auto issue_k = [&](int tile, int st) {
        const int s0 = tile * 64;
        #pragma unroll
        for (int i = 0; i < 8; i++) {
            const int idx = tid + i * 128;
            const int r = idx >> 4, c4 = (idx & 15) * 4;
            CP_ASYNC16(smem_u32(&Ks[st * 4352 + r * 68 + c4]),
                       &g_kqv[(size_t)(b * TSEQ + s0 + r) * D3 + h * HD + c4]);
        }
        CP_COMMIT();
    };
    auto issue_v = [&](int tile) {
        const int s0 = tile * 64;
        #pragma unroll
        for (int i = 0; i < 8; i++) {
            const int idx = tid + i * 128;
            const int r = idx >> 4, c4 = (idx & 15) * 4;
            CP_ASYNC16(smem_u32(&Vs[r * 72 + c4]),
                       &g_kqv[(size_t)(b * TSEQ + s0 + r) * D3 + 2 * DM + h * HD + c4]);
        }
        CP_COMMIT();
    };

    // prologue: K(0) then V(0) in flight
    issue_k(0, 0);
    issue_v(0);

    // Load Q tile (plain LDG->STS; rounded tf32 already)
    #pragma unroll
    for (int i = 0; i < 8; i++) {
        const int idx = tid + i * 128;
        const int r = idx >> 4, c4 = (idx & 15) * 4;
        *reinterpret_cast<float4*>(&Qs[r * 68 + c4]) =
            *reinterpret_cast<const float4*>(
                &g_kqv[(size_t)(b * TSEQ + q0 + r) * D3 + DM + h * HD + c4]);
    }
    __syncthreads();   // Qs visible -> hoist Q fragments, then Qs region is Ps

    uint32_t qf[8][4];
    {
        const uint32_t q_addr = smem_u32(Qs) + a_lane_off;
        #pragma unroll
        for (int ksn = 0; ksn < 8; ksn++)
            LDSM_X4(qf[ksn][0], qf[ksn][1], qf[ksn][2], qf[ksn][3],
                    q_addr + (uint32_t)ksn * 32);
    }

    float o[8][4];
    #pragma unroll
    for (int nt = 0; nt < 8; nt++)
        #pragma unroll
        for (int e = 0; e < 4; e++) o[nt][e] = 0.0f;
    float m_lo = -1e30f, m_hi = -1e30f, l_lo = 0.0f, l_hi = 0.0f;

    const uint32_t p_addr = smem_u32(Ps) + a_lane_off;

    for (int tile = 0; tile <= qb; tile++) {
        const int s0 = tile * 64;
        const int st = tile & 1;
        const bool more = (tile + 1 <= qb);
        if (more) { issue_k(tile + 1, st ^ 1); CP_WAIT2(); }  // allow {V(t), K(t+1)}
        else      { CP_WAIT1(); }                              // allow {V(t)}
        __syncthreads();     // K(st) visible

        const uint32_t k_addr = smem_u32(Ks) + (uint32_t)st * 4352 * 4 + k_lane_off;

        // ---- S = Q @ K^T ----
        float sacc[8][4];
        #pragma unroll
        for (int nt = 0; nt < 8; nt++)
            #pragma unroll
            for (int e = 0; e < 4; e++) sacc[nt][e] = 0.0f;

        #pragma unroll
        for (int ksn = 0; ksn < 8; ksn++) {
            const int k = ksn * 8;
            #pragma unroll
            for (int nt = 0; nt < 8; nt += 2) {
                uint32_t b0a, b1a, b0b, b1b;
                LDSM_X4(b0a, b1a, b0b, b1b,
                        k_addr + (uint32_t)(nt * 8 * 68 + k) * 4);
                MMA_TF32(sacc[nt],     qf[ksn][0], qf[ksn][1], qf[ksn][2], qf[ksn][3], b0a, b1a);
                MMA_TF32(sacc[nt + 1], qf[ksn][0], qf[ksn][1], qf[ksn][2], qf[ksn][3], b0b, b1b);
            }
        }

        // ---- scale (log2 domain) + causal mask (diagonal tile only) ----
        const bool masked = (tile == qb);
        #pragma unroll
        for (int nt = 0; nt < 8; nt++) {
            float v0 = sacc[nt][0] * ASC, v1 = sacc[nt][1] * ASC;
            float v2 = sacc[nt][2] * ASC, v3 = sacc[nt][3] * ASC;
            if (masked) {
                const int c0 = s0 + nt * 8 + 2 * tig, c1 = c0 + 1;
                if (c0 > r_lo_g) v0 = -1e30f;
                if (c1 > r_lo_g) v1 = -1e30f;
                if (c0 > r_hi_g) v2 = -1e30f;
                if (c1 > r_hi_g) v3 = -1e30f;
            }
            sacc[nt][0] = v0; sacc[nt][1] = v1; sacc[nt][2] = v2; sacc[nt][3] = v3;
        }

        // ---- online softmax ----
        float xl = -1e30f, xh = -1e30f;
        #pragma unroll
        for (int nt = 0; nt < 8; nt++) {
            xl = fmaxf(xl, fmaxf(sacc[nt][0], sacc[nt][1]));
            xh = fmaxf(xh, fmaxf(sacc[nt][2], sacc[nt][3]));
        }
        xl = fmaxf(xl, __shfl_xor_sync(0xFFFFFFFFu, xl, 1));
        xl = fmaxf(xl, __shfl_xor_sync(0xFFFFFFFFu, xl, 2));
        xh = fmaxf(xh, __shfl_xor_sync(0xFFFFFFFFu, xh, 1));
        xh = fmaxf(xh, __shfl_xor_sync(0xFFFFFFFFu, xh, 2));
        const float mn_lo = fmaxf(m_lo, xl);
        const float mn_hi = fmaxf(m_hi, xh);
        const float al = exp2f(m_lo - mn_lo);
        const float ah = exp2f(m_hi - mn_hi);
        m_lo = mn_lo; m_hi = mn_hi;

        float sl = 0.0f, sh = 0.0f;
        #pragma unroll
        for (int nt = 0; nt < 8; nt++) {
            const float p0 = exp2f(sacc[nt][0] - mn_lo);
            const float p1 = exp2f(sacc[nt][1] - mn_lo);
            const float p2 = exp2f(sacc[nt][2] - mn_hi);
            const float p3 = exp2f(sacc[nt][3] - mn_hi);
            sl += p0 + p1; sh += p2 + p3;
            const int c = nt * 8 + 2 * tig;
            *reinterpret_cast<float2*>(&Ps[(wr + g) * PS + c]) =
                make_float2(tf32_rna(p0), tf32_rna(p1));
            *reinterpret_cast<float2*>(&Ps[(wr + g + 8) * PS + c]) =
                make_float2(tf32_rna(p2), tf32_rna(p3));
        }
        sl += __shfl_xor_sync(0xFFFFFFFFu, sl, 1);
        sl += __shfl_xor_sync(0xFFFFFFFFu, sl, 2);
        sh += __shfl_xor_sync(0xFFFFFFFFu, sh, 1);
        sh += __shfl_xor_sync(0xFFFFFFFFu, sh, 2);
        l_lo = l_lo * al + sl;
        l_hi = l_hi * ah + sh;
        #pragma unroll
        for (int nt = 0; nt < 8; nt++) {
            o[nt][0] *= al; o[nt][1] *= al;
            o[nt][2] *= ah; o[nt][3] *= ah;
        }
        __syncwarp();

        // ---- wait V(t), then O += P @ V ----
        if (more) CP_WAIT1(); else CP_WAIT0();   // allow K(t+1) only
        __syncthreads();     // V visible to all threads

        #pragma unroll
        for (int ksn = 0; ksn < 8; ksn++) {
            const int k = ksn * 8;
            uint32_t pa0, pa1, pa2, pa3;
            LDSM_X4(pa0, pa1, pa2, pa3, p_addr + (uint32_t)ksn * 32);
            #pragma unroll
            for (int nt = 0; nt < 8; nt++) {
                const uint32_t b0 = __float_as_uint(Vs[(k + tig) * 72 + nt * 8 + g]);
                const uint32_t b1 = __float_as_uint(Vs[(k + tig + 4) * 72 + nt * 8 + g]);
                MMA_TF32(o[nt], pa0, pa1, pa2, pa3, b0, b1);
            }
        }
        __syncthreads();     // all warps done reading Vs before refill
        if (more) issue_v(tile + 1);
    }

    // epilogue: normalize, round to tf32 (GEMM2 consumes as A), store
    const float il = 1.0f / l_lo;
    const float ih = 1.0f / l_hi;
    #pragma unroll
    for (int nt = 0; nt < 8; nt++) {
        const int c = h * HD + nt * 8 + 2 * tig;
        *reinterpret_cast<float2*>(&g_att[(size_t)(b * TSEQ + r_lo_g) * DM + c]) =
            make_float2(tf32_rna(o[nt][0] * il), tf32_rna(o[nt][1] * il));
        *reinterpret_cast<float2*>(&g_att[(size_t)(b * TSEQ + r_hi_g) * DM + c]) =
            make_float2(tf32_rna(o[nt][2] * ih), tf32_rna(o[nt][3] * ih));
    }
}

// ----------------------------------------------------------------------------
extern "C" void kernel_launch(void* const* d_in, const int* in_sizes, int n_in,
                              void* d_out, int out_size)
{
    (void)in_sizes; (void)n_in; (void)out_size;
    const float* x     = (const float*)d_in[0];
    const float* W_kqv = (const float*)d_in[1];
    const float* b_kqv = (const float*)d_in[2];
    const float* W_o   = (const float*)d_in[3];
    const float* b_o   = (const float*)d_in[4];
    float* out = (float*)d_out;

    float *kqv_p, *att_p, *xa_p, *wk_p, *wo_p;
    cudaGetSymbolAddress((void**)&kqv_p, g_kqv);
    cudaGetSymbolAddress((void**)&att_p, g_att);
    cudaGetSymbolAddress((void**)&xa_p,  g_xa);
    cudaGetSymbolAddress((void**)&wk_p,  g_wk);
    cudaGetSymbolAddress((void**)&wo_p,  g_wo);

    cudaFuncSetAttribute(gemm_mma_kernel,
                         cudaFuncAttributeMaxDynamicSharedMemorySize, G_SMEM_BYTES);
    cudaFuncSetAttribute(attn_mma_kernel,
                         cudaFuncAttributeMaxDynamicSharedMemorySize, A_SMEM_BYTES);

    // prep: single merged tf32 rounding pass (x, W_kqv, W_o)
    round_all_kernel<<<N_PREP / 256, 256>>>(x, W_kqv, W_o);

    // 1) KQV projection (outputs rounded to tf32 for attention)
    gemm_mma_kernel<<<dim3(D3 / 128, BT / 128), 256, G_SMEM_BYTES>>>(
        xa_p, wk_p, b_kqv, kqv_p, BT, D3, DM, 1);
    // 2) Causal flash attention (occ 3, K double-buffer)
    attn_mma_kernel<<<dim3(TSEQ / 64, NH, NB), 128, A_SMEM_BYTES>>>();
    // 3) Output projection
    gemm_mma_kernel<<<dim3(DM / 128, BT / 128), 256, G_SMEM_BYTES>>>(
        att_p, wo_p, b_o, out, BT, DM, DM, 0);
}